// round 12
// baseline (speedup 1.0000x reference)
#include <cuda_runtime.h>
#include <cuda_fp16.h>

#define HID 256
#define G4  1024
#define NE  64
#define BAT 256
#define NSTEP 6
#define RK  16

// ---------------- scratch (allocation-free: device globals) ----------------
__device__ __align__(16) float   g_xg[NE * G4];      // fp32 gate-interleaved [j][k][4]
__device__ __align__(16) uint2   g_xgh[NE * HID];    // fp16 (i,f)(g,o) packed, 8B per (j,k)
__device__ __align__(16) __half2 g_whh2[128 * G4];   // PW[kp][m] = (WhhT[2kp][m], WhhT[2kp+1][m])
__device__ __align__(16) __half2 g_wm2[128 * HID];   // PM[kp][m]
__device__ __align__(16) float   g_h0[NE * HID];
__device__ __align__(16) float   g_c0[NE * HID];
__device__ __align__(16) float   g_sout[NE * RK];

// ---------------- transcendentals ------------------------------------------
__device__ __forceinline__ float tap(float x){ float y; asm("tanh.approx.f32 %0,%1;" : "=f"(y) : "f"(x)); return y; }
__device__ __forceinline__ float frcp(float x){ float y; asm("rcp.approx.f32 %0,%1;" : "=f"(y) : "f"(x)); return y; }
__device__ __forceinline__ float sigm(float x){ return fmaf(0.5f, tap(0.5f * x), 0.5f); }
__device__ __forceinline__ float2 h2f(__half2 h){ return __half22float2(h); }
__device__ __forceinline__ __half2 tanh2(__half2 x){
    unsigned r; unsigned xi = *reinterpret_cast<unsigned*>(&x);
    asm("tanh.approx.f16x2 %0,%1;" : "=r"(r) : "r"(xi));
    return *reinterpret_cast<__half2*>(&r);
}
__device__ __forceinline__ __half2 sigm2(__half2 x, __half2 h05){
    return __hfma2(h05, tanh2(__hmul2(h05, x)), h05);
}

// ============================================================================
// K_prep: unchanged from the 124.7/124.9us kernels.
// ============================================================================
__global__ __launch_bounds__(256) void k_prep(const float* __restrict__ emb,
                                              const float* __restrict__ Wih,
                                              const float* __restrict__ bih,
                                              const float* __restrict__ bhh,
                                              const float* __restrict__ Whh,
                                              const float* __restrict__ Wm)
{
    __shared__ __align__(16) union {
        struct { __half As[256][34]; float Bs[64][68]; } g;
        float T[64 * 65];
    } SP;
    const int id = blockIdx.x, t = threadIdx.x;

    if (id < 32) {
        const int tx = t & 15, ty = t >> 4;
        const int jb0 = (id & 1) * 32;
        const int m0  = (id >> 1) * 64;
        {
            const int jrow = t >> 3;
            const int c0 = (t & 7) * 32;
            #pragma unroll
            for (int i = 0; i < 8; i++) {
                const float4 v = *(const float4*)&emb[(jb0 + jrow) * HID + c0 + 4 * i];
                SP.g.As[c0 + 4*i + 0][jrow] = __float2half(v.x);
                SP.g.As[c0 + 4*i + 1][jrow] = __float2half(v.y);
                SP.g.As[c0 + 4*i + 2][jrow] = __float2half(v.z);
                SP.g.As[c0 + 4*i + 3][jrow] = __float2half(v.w);
            }
        }
        const int br = t >> 4;
        const int bc4 = (t & 15) * 4;
        float4 pf0, pf1, pf2, pf3;
        {
            pf0 = *(const float4*)&Wih[(m0 + br +  0) * HID + bc4];
            pf1 = *(const float4*)&Wih[(m0 + br + 16) * HID + bc4];
            pf2 = *(const float4*)&Wih[(m0 + br + 32) * HID + bc4];
            pf3 = *(const float4*)&Wih[(m0 + br + 48) * HID + bc4];
        }
        float acc[2][4] = {};
        for (int ch = 0; ch < 4; ch++) {
            SP.g.Bs[bc4+0][br+ 0] = pf0.x; SP.g.Bs[bc4+1][br+ 0] = pf0.y;
            SP.g.Bs[bc4+2][br+ 0] = pf0.z; SP.g.Bs[bc4+3][br+ 0] = pf0.w;
            SP.g.Bs[bc4+0][br+16] = pf1.x; SP.g.Bs[bc4+1][br+16] = pf1.y;
            SP.g.Bs[bc4+2][br+16] = pf1.z; SP.g.Bs[bc4+3][br+16] = pf1.w;
            SP.g.Bs[bc4+0][br+32] = pf2.x; SP.g.Bs[bc4+1][br+32] = pf2.y;
            SP.g.Bs[bc4+2][br+32] = pf2.z; SP.g.Bs[bc4+3][br+32] = pf2.w;
            SP.g.Bs[bc4+0][br+48] = pf3.x; SP.g.Bs[bc4+1][br+48] = pf3.y;
            SP.g.Bs[bc4+2][br+48] = pf3.z; SP.g.Bs[bc4+3][br+48] = pf3.w;
            if (ch < 3) {
                const int kb = 64 * (ch + 1);
                pf0 = *(const float4*)&Wih[(m0 + br +  0) * HID + kb + bc4];
                pf1 = *(const float4*)&Wih[(m0 + br + 16) * HID + kb + bc4];
                pf2 = *(const float4*)&Wih[(m0 + br + 32) * HID + kb + bc4];
                pf3 = *(const float4*)&Wih[(m0 + br + 48) * HID + kb + bc4];
            }
            __syncthreads();
            const int kg = 64 * ch;
            #pragma unroll 8
            for (int kk = 0; kk < 64; kk++) {
                const float2 a = h2f(*(const __half2*)&SP.g.As[kg + kk][2 * ty]);
                const float4 bv = *(const float4*)&SP.g.Bs[kk][4 * tx];
                acc[0][0] = fmaf(a.x, bv.x, acc[0][0]); acc[0][1] = fmaf(a.x, bv.y, acc[0][1]);
                acc[0][2] = fmaf(a.x, bv.z, acc[0][2]); acc[0][3] = fmaf(a.x, bv.w, acc[0][3]);
                acc[1][0] = fmaf(a.y, bv.x, acc[1][0]); acc[1][1] = fmaf(a.y, bv.y, acc[1][1]);
                acc[1][2] = fmaf(a.y, bv.z, acc[1][2]); acc[1][3] = fmaf(a.y, bv.w, acc[1][3]);
            }
            __syncthreads();
        }
        const int mc0 = m0 + 4 * tx;
        const int gate = mc0 >> 8;
        const int kc0  = mc0 & 255;
        float bias[4];
        #pragma unroll
        for (int jj = 0; jj < 4; jj++) bias[jj] = bih[mc0 + jj] + bhh[mc0 + jj];
        #pragma unroll
        for (int i = 0; i < 2; i++) {
            const int jr = jb0 + 2 * ty + i;
            #pragma unroll
            for (int jj = 0; jj < 4; jj++)
                g_xg[jr * G4 + 4 * (kc0 + jj) + gate] = acc[i][jj] + bias[jj];
        }
    } else {
        const bool isWhh = (id < 96);
        const int tid = isWhh ? (id - 32) : (id - 96);
        const int mi  = isWhh ? (tid & 15) : (tid & 3);
        const int ki  = isWhh ? (tid >> 4) : (tid >> 2);
        const float* __restrict__ src = isWhh ? Whh : Wm;
        {
            const int c4 = (t & 15) * 4;
            const int r0 = t >> 4;
            const float4 v0 = *(const float4*)&src[(mi * 64 + r0 +  0) * HID + ki * 64 + c4];
            const float4 v1 = *(const float4*)&src[(mi * 64 + r0 + 16) * HID + ki * 64 + c4];
            const float4 v2 = *(const float4*)&src[(mi * 64 + r0 + 32) * HID + ki * 64 + c4];
            const float4 v3 = *(const float4*)&src[(mi * 64 + r0 + 48) * HID + ki * 64 + c4];
            float* T0 = SP.T + (r0 +  0) * 65; float* T1 = SP.T + (r0 + 16) * 65;
            float* T2 = SP.T + (r0 + 32) * 65; float* T3 = SP.T + (r0 + 48) * 65;
            T0[c4+0] = v0.x; T0[c4+1] = v0.y; T0[c4+2] = v0.z; T0[c4+3] = v0.w;
            T1[c4+0] = v1.x; T1[c4+1] = v1.y; T1[c4+2] = v1.z; T1[c4+3] = v1.w;
            T2[c4+0] = v2.x; T2[c4+1] = v2.y; T2[c4+2] = v2.z; T2[c4+3] = v2.w;
            T3[c4+0] = v3.x; T3[c4+1] = v3.y; T3[c4+2] = v3.z; T3[c4+3] = v3.w;
        }
        __syncthreads();
        const int m_l = t & 63, kp0 = t >> 6;
        const int rowlen = isWhh ? G4 : HID;
        __half2* __restrict__ dst = isWhh ? g_whh2 : g_wm2;
        #pragma unroll
        for (int i = 0; i < 8; i++) {
            const int kpl = kp0 + 4 * i;
            const __half2 h2 = __floats2half2_rn(SP.T[m_l * 65 + 2 * kpl], SP.T[m_l * 65 + 2 * kpl + 1]);
            dst[(ki * 32 + kpl) * rowlen + mi * 64 + m_l] = h2;
        }
    }
}

// ============================================================================
// K_h0: unchanged.
// ============================================================================
__global__ __launch_bounds__(256) void k_h0(const float* __restrict__ Wf,
                                            const float* __restrict__ bf)
{
    __shared__ float sh0[HID];
    const int j = blockIdx.x, t = threadIdx.x;
    const float4 x4 = ((const float4*)g_xg)[j * HID + t];   // (i,f,g,o)
    {
        union { __half2 h2[2]; uint2 u; } p;
        p.h2[0] = __floats2half2_rn(x4.x, x4.y);
        p.h2[1] = __floats2half2_rn(x4.z, x4.w);
        g_xgh[j * HID + t] = p.u;
    }
    const float c0 = sigm(x4.x) * tap(x4.z);
    const float h0 = sigm(x4.w) * tap(c0);
    g_c0[j * HID + t] = c0;
    g_h0[j * HID + t] = h0;
    sh0[t] = h0;
    __syncthreads();
    const int w = t >> 5, l = t & 31;
    #pragma unroll
    for (int rr = 0; rr < 2; rr++) {
        const int r = w + 8 * rr;
        float a = 0.f;
        #pragma unroll
        for (int q = 0; q < 8; q++) {
            const int k = l + 32 * q;
            a = fmaf(sh0[k], Wf[r * HID + k], a);
        }
        a += __shfl_xor_sync(0xFFFFFFFFu, a, 16);
        a += __shfl_xor_sync(0xFFFFFFFFu, a, 8);
        a += __shfl_xor_sync(0xFFFFFFFFu, a, 4);
        a += __shfl_xor_sync(0xFFFFFFFFu, a, 2);
        a += __shfl_xor_sync(0xFFFFFFFFu, a, 1);
        if (l == 0) g_sout[j * RK + r] = a + bf[r];
    }
}

// ============================================================================
// K_chain: 128 blocks x 512 thr.
// Round-12 deltas vs the 124.7us version:
//  (1) GEMV weight loads use __ldcg -> whh2 stream stays out of L1, so g_xgh
//      (128KB) + g_wm2 (128KB) stay L1-resident across steps (L1 persists
//      within a launch).
//  (2) Cell hsum loop in f16x2 packed over the batch pair (tanh.approx.f16x2):
//      5 MUFU per (j,k) instead of 10. hsum accumulated in f32. Denominators
//      are bias-dominated (64*bm ~ 32) so f16 hsum noise -> ~1e-5 relative.
//  (3) The recurrence-carried hsel/csel recomputed in FULL f32 for the one
//      selected j per batch (from fp32 g_xg) -> no error compounding.
// ============================================================================
__global__ __launch_bounds__(512) void k_chain(const int* __restrict__ xidx,
                                               const float* __restrict__ bm,
                                               const float* __restrict__ Wl,
                                               const float* __restrict__ bl,
                                               float* __restrict__ out)
{
    __shared__ __align__(16) float sh_h[2][HID];
    __shared__ __align__(16) float sh_c[2][HID];
    __shared__ __align__(16) float sh_hgp[2][2][G4];   // GEMV partials; [0] = combined hg
    __shared__ __align__(16) float s_cur[2][HID];
    __shared__ float st_tot[2][RK];
    __shared__ float s_rcl[RK];

    const int t = threadIdx.x;
    const int half = t >> 8, tt = t & 255;
    const int b0 = blockIdx.x * 2;
    float* s_hs = &sh_hgp[1][0][0];         // hsum partials / combined
    float* s_md = &sh_hgp[0][0][0];         // mid partials (hg dead)
    const __half2 h05 = __float2half2_rn(0.5f);

    // ---- Phase A: step-0 normalize + gather ----
    if (t < RK) {
        float s = 0.f;
        #pragma unroll 8
        for (int j = 0; j < NE; j++) s += g_sout[j * RK + t];
        s_rcl[t] = 1.0f / s;
    }
    {
        const int sel = xidx[(b0 + half) * NSTEP + 0];
        sh_h[half][tt] = g_h0[sel * HID + tt];
        sh_c[half][tt] = g_c0[sel * HID + tt];
    }
    __syncthreads();
    if (t < 2 * RK) {
        const int b = t >> 4, r = t & 15;
        const int sel = xidx[(b0 + b) * NSTEP + 0];
        st_tot[b][r] = g_sout[sel * RK + r] * s_rcl[r];
    }

    for (int s = 1; s < NSTEP; s++) {
        __syncthreads();
        // ---- GEMV: hg[b][m] = sum_k h[b][k]*WhhT[k][m]; kp-split by half ----
        {
            const int kpb = half * 64;
            const int mb  = tt * 4;
            float4 ac0 = {0,0,0,0}, ac1 = {0,0,0,0};
            #pragma unroll 4
            for (int kp = 0; kp < 64; kp++) {
                const uint4 w = __ldcg((const uint4*)&g_whh2[(kpb + kp) * G4 + mb]);
                const float2 hA = *(const float2*)&sh_h[0][2 * (kpb + kp)];
                const float2 hB = *(const float2*)&sh_h[1][2 * (kpb + kp)];
                const float2 p0 = h2f(*(const __half2*)&w.x);
                const float2 p1 = h2f(*(const __half2*)&w.y);
                const float2 p2 = h2f(*(const __half2*)&w.z);
                const float2 p3 = h2f(*(const __half2*)&w.w);
                ac0.x = fmaf(hA.x, p0.x, fmaf(hA.y, p0.y, ac0.x));
                ac0.y = fmaf(hA.x, p1.x, fmaf(hA.y, p1.y, ac0.y));
                ac0.z = fmaf(hA.x, p2.x, fmaf(hA.y, p2.y, ac0.z));
                ac0.w = fmaf(hA.x, p3.x, fmaf(hA.y, p3.y, ac0.w));
                ac1.x = fmaf(hB.x, p0.x, fmaf(hB.y, p0.y, ac1.x));
                ac1.y = fmaf(hB.x, p1.x, fmaf(hB.y, p1.y, ac1.y));
                ac1.z = fmaf(hB.x, p2.x, fmaf(hB.y, p2.y, ac1.z));
                ac1.w = fmaf(hB.x, p3.x, fmaf(hB.y, p3.y, ac1.w));
            }
            *(float4*)&sh_hgp[half][0][mb] = ac0;
            *(float4*)&sh_hgp[half][1][mb] = ac1;
        }
        __syncthreads();
        {   // combine k-halves
            const int lin = t * 4;
            float4 a = *(const float4*)(&sh_hgp[0][0][0] + lin);
            const float4 b = *(const float4*)(&sh_hgp[1][0][0] + lin);
            a.x += b.x; a.y += b.y; a.z += b.z; a.w += b.w;
            *(float4*)(&sh_hgp[0][0][0] + lin) = a;
        }
        __syncthreads();
        // ---- CELL: j-split by half (32 j each), k = tt ----
        const int selb0 = xidx[b0 * NSTEP + s];
        const int selb1 = xidx[(b0 + 1) * NSTEP + s];
        const int k = tt;
        const float hgI0 = sh_hgp[0][0][k],         hgF0 = sh_hgp[0][0][HID + k];
        const float hgG0 = sh_hgp[0][0][2*HID + k], hgO0 = sh_hgp[0][0][3*HID + k];
        const float hgI1 = sh_hgp[0][1][k],         hgF1 = sh_hgp[0][1][HID + k];
        const float hgG1 = sh_hgp[0][1][2*HID + k], hgO1 = sh_hgp[0][1][3*HID + k];
        const float cp0 = sh_c[0][k], cp1 = sh_c[1][k];
        __syncthreads();   // reads of sh_c / gates done before owners overwrite
        // f16x2 packed over (b0, b1)
        const __half2 HgI = __floats2half2_rn(hgI0, hgI1);
        const __half2 HgF = __floats2half2_rn(hgF0, hgF1);
        const __half2 HgG = __floats2half2_rn(hgG0, hgG1);
        const __half2 HgO = __floats2half2_rn(hgO0, hgO1);
        const __half2 cp2 = __floats2half2_rn(cp0, cp1);
        float hs0 = 0.f, hs1 = 0.f;
        const int jb = half * 32;
        #pragma unroll 4
        for (int j = jb; j < jb + 32; j++) {
            const uint2 u = g_xgh[j * HID + k];
            const __half2 xif = *(const __half2*)&u.x;   // (xi, xf)
            const __half2 xgo = *(const __half2*)&u.y;   // (xg, xo)
            const __half2 gi = __hadd2(__low2half2 (xif), HgI);
            const __half2 gf = __hadd2(__high2half2(xif), HgF);
            const __half2 gg = __hadd2(__low2half2 (xgo), HgG);
            const __half2 go = __hadd2(__high2half2(xgo), HgO);
            const __half2 iv = sigm2(gi, h05);
            const __half2 fv = sigm2(gf, h05);
            const __half2 gv = tanh2(gg);
            const __half2 ov = sigm2(go, h05);
            const __half2 cn = __hfma2(fv, cp2, __hmul2(iv, gv));
            const __half2 hn = __hmul2(ov, tanh2(cn));
            const float2 hf = h2f(hn);
            hs0 += hf.x; hs1 += hf.y;
        }
        s_hs[(half * 2 + 0) * HID + k] = hs0;
        s_hs[(half * 2 + 1) * HID + k] = hs1;
        // selected-j recompute in FULL f32 (recurrence-carried state)
        if ((selb0 >> 5) == half) {
            const float4 x = ((const float4*)g_xg)[selb0 * HID + k];
            const float iv = sigm(x.x + hgI0), fv = sigm(x.y + hgF0);
            const float gv = tap (x.z + hgG0), ov = sigm(x.w + hgO0);
            const float cn = fmaf(fv, cp0, iv * gv);
            sh_h[0][k] = ov * tap(cn); sh_c[0][k] = cn;
        }
        if ((selb1 >> 5) == half) {
            const float4 x = ((const float4*)g_xg)[selb1 * HID + k];
            const float iv = sigm(x.x + hgI1), fv = sigm(x.y + hgF1);
            const float gv = tap (x.z + hgG1), ov = sigm(x.w + hgO1);
            const float cn = fmaf(fv, cp1, iv * gv);
            sh_h[1][k] = ov * tap(cn); sh_c[1][k] = cn;
        }
        __syncthreads();
        {   // combine hsum halves
            const int b = t >> 8, k2 = t & 255;
            s_hs[b * HID + k2] += s_hs[(2 + b) * HID + k2];
        }
        __syncthreads();

        if (s < NSTEP - 1) {
            // ---- MID: num/den GEMV vs WmT (kp-split), total @= cur ----
            const int kpb = half * 64;
            const int m = tt;
            float n0 = 0.f, n1 = 0.f, d0 = 0.f, d1 = 0.f;
            #pragma unroll 4
            for (int kp = 0; kp < 64; kp++) {
                const float2 w = h2f(g_wm2[(kpb + kp) * HID + m]);
                const float2 hA = *(const float2*)&sh_h[0][2 * (kpb + kp)];
                const float2 hB = *(const float2*)&sh_h[1][2 * (kpb + kp)];
                const float2 uA = *(const float2*)&s_hs[0 * HID + 2 * (kpb + kp)];
                const float2 uB = *(const float2*)&s_hs[1 * HID + 2 * (kpb + kp)];
                n0 = fmaf(w.x, hA.x, fmaf(w.y, hA.y, n0));
                n1 = fmaf(w.x, hB.x, fmaf(w.y, hB.y, n1));
                d0 = fmaf(w.x, uA.x, fmaf(w.y, uA.y, d0));
                d1 = fmaf(w.x, uB.x, fmaf(w.y, uB.y, d1));
            }
            s_md[(half * 4 + 0) * HID + m] = n0;
            s_md[(half * 4 + 1) * HID + m] = n1;
            s_md[(half * 4 + 2) * HID + m] = d0;
            s_md[(half * 4 + 3) * HID + m] = d1;
            __syncthreads();
            if (half == 0) {
                const float n0f = s_md[0 * HID + tt] + s_md[4 * HID + tt];
                const float n1f = s_md[1 * HID + tt] + s_md[5 * HID + tt];
                const float d0f = s_md[2 * HID + tt] + s_md[6 * HID + tt];
                const float d1f = s_md[3 * HID + tt] + s_md[7 * HID + tt];
                const float bmv = bm[tt];
                s_cur[0][tt] = (n0f + bmv) * frcp(d0f + 64.0f * bmv);
                s_cur[1][tt] = (n1f + bmv) * frcp(d1f + 64.0f * bmv);
            }
            __syncthreads();
            float ntot = 0.f;
            const int ub = t >> 4, ur = t & 15;
            if (t < 32) {
                #pragma unroll
                for (int r1 = 0; r1 < RK; r1++)
                    ntot = fmaf(st_tot[ub][r1], s_cur[ub][r1 * RK + ur], ntot);
            }
            __syncthreads();
            if (t < 32) st_tot[ub][ur] = ntot;
        } else {
            // ---- FINAL ----
            if (t < 64) {
                const int b = t >> 5, l = t & 31;
                const int r = l & 15, role = l >> 4;
                const float* __restrict__ src = role ? (s_hs + b * HID) : &sh_h[b][0];
                float acc = 0.f;
                #pragma unroll 8
                for (int kk = 0; kk < HID; kk++)
                    acc = fmaf(Wl[r * HID + kk], src[kk], acc);
                acc += (role ? 64.0f : 1.0f) * bl[r];
                const float den = __shfl_down_sync(0xFFFFFFFFu, acc, 16);
                float v = 0.f;
                if (!role) v = st_tot[b][r] * acc * frcp(den);
                v += __shfl_xor_sync(0xFFFFFFFFu, v, 8);
                v += __shfl_xor_sync(0xFFFFFFFFu, v, 4);
                v += __shfl_xor_sync(0xFFFFFFFFu, v, 2);
                v += __shfl_xor_sync(0xFFFFFFFFu, v, 1);
                if (l == 0) out[b0 + b] = v;
            }
        }
    }
}

// ============================================================================
extern "C" void kernel_launch(void* const* d_in, const int* in_sizes, int n_in,
                              void* d_out, int out_size)
{
    (void)in_sizes; (void)n_in; (void)out_size;
    const int*   x_idx = (const int*)  d_in[0];
    const float* emb   = (const float*)d_in[1];
    const float* Wih   = (const float*)d_in[2];
    const float* Whh   = (const float*)d_in[3];
    const float* bih   = (const float*)d_in[4];
    const float* bhh   = (const float*)d_in[5];
    const float* Wf    = (const float*)d_in[6];
    const float* bf    = (const float*)d_in[7];
    const float* Wm    = (const float*)d_in[8];
    const float* bm    = (const float*)d_in[9];
    const float* Wl    = (const float*)d_in[10];
    const float* bl    = (const float*)d_in[11];
    float* out = (float*)d_out;

    k_prep <<<112, 256>>>(emb, Wih, bih, bhh, Whh, Wm);
    k_h0   <<<NE, 256>>>(Wf, bf);
    k_chain<<<BAT / 2, 512>>>(x_idx, bm, Wl, bl, out);
}

// round 13
// speedup vs baseline: 1.1295x; 1.1295x over previous
#include <cuda_runtime.h>
#include <cuda_fp16.h>

#define HID 256
#define G4  1024
#define NE  64
#define BAT 256
#define NSTEP 6
#define RK  16

// ---------------- scratch (allocation-free: device globals) ----------------
__device__ __align__(16) float   g_xg[NE * G4];      // fp32 gate-interleaved [j][k][4]
__device__ __align__(16) uint2   g_xgh[NE * HID];    // fp16 (i,f)(g,o) packed
__device__ __align__(16) __half2 g_whh2[128 * G4];   // PW[kp][m]
__device__ __align__(16) __half2 g_wm2[128 * HID];   // PM[kp][m]
__device__ __align__(16) float   g_h0[NE * HID];
__device__ __align__(16) float   g_c0[NE * HID];
__device__ __align__(16) float   g_sout[NE * RK];

// ---------------- transcendentals ------------------------------------------
__device__ __forceinline__ float tap(float x){ float y; asm("tanh.approx.f32 %0,%1;" : "=f"(y) : "f"(x)); return y; }
__device__ __forceinline__ float frcp(float x){ float y; asm("rcp.approx.f32 %0,%1;" : "=f"(y) : "f"(x)); return y; }
__device__ __forceinline__ float sigm(float x){ return fmaf(0.5f, tap(0.5f * x), 0.5f); }
__device__ __forceinline__ float2 h2f(__half2 h){ return __half22float2(h); }
__device__ __forceinline__ __half2 tanh2(__half2 x){
    unsigned r; unsigned xi = *reinterpret_cast<unsigned*>(&x);
    asm("tanh.approx.f16x2 %0,%1;" : "=r"(r) : "r"(xi));
    return *reinterpret_cast<__half2*>(&r);
}
__device__ __forceinline__ __half2 sigm2(__half2 x, __half2 h05){
    return __hfma2(h05, tanh2(__hmul2(h05, x)), h05);
}

// ============================================================================
// K_prep: unchanged (rounds 11/12).
// ============================================================================
__global__ __launch_bounds__(256) void k_prep(const float* __restrict__ emb,
                                              const float* __restrict__ Wih,
                                              const float* __restrict__ bih,
                                              const float* __restrict__ bhh,
                                              const float* __restrict__ Whh,
                                              const float* __restrict__ Wm)
{
    __shared__ __align__(16) union {
        struct { __half As[256][34]; float Bs[64][68]; } g;
        float T[64 * 65];
    } SP;
    const int id = blockIdx.x, t = threadIdx.x;

    if (id < 32) {
        const int tx = t & 15, ty = t >> 4;
        const int jb0 = (id & 1) * 32;
        const int m0  = (id >> 1) * 64;
        {
            const int jrow = t >> 3;
            const int c0 = (t & 7) * 32;
            #pragma unroll
            for (int i = 0; i < 8; i++) {
                const float4 v = *(const float4*)&emb[(jb0 + jrow) * HID + c0 + 4 * i];
                SP.g.As[c0 + 4*i + 0][jrow] = __float2half(v.x);
                SP.g.As[c0 + 4*i + 1][jrow] = __float2half(v.y);
                SP.g.As[c0 + 4*i + 2][jrow] = __float2half(v.z);
                SP.g.As[c0 + 4*i + 3][jrow] = __float2half(v.w);
            }
        }
        const int br = t >> 4;
        const int bc4 = (t & 15) * 4;
        float4 pf0, pf1, pf2, pf3;
        {
            pf0 = *(const float4*)&Wih[(m0 + br +  0) * HID + bc4];
            pf1 = *(const float4*)&Wih[(m0 + br + 16) * HID + bc4];
            pf2 = *(const float4*)&Wih[(m0 + br + 32) * HID + bc4];
            pf3 = *(const float4*)&Wih[(m0 + br + 48) * HID + bc4];
        }
        float acc[2][4] = {};
        for (int ch = 0; ch < 4; ch++) {
            SP.g.Bs[bc4+0][br+ 0] = pf0.x; SP.g.Bs[bc4+1][br+ 0] = pf0.y;
            SP.g.Bs[bc4+2][br+ 0] = pf0.z; SP.g.Bs[bc4+3][br+ 0] = pf0.w;
            SP.g.Bs[bc4+0][br+16] = pf1.x; SP.g.Bs[bc4+1][br+16] = pf1.y;
            SP.g.Bs[bc4+2][br+16] = pf1.z; SP.g.Bs[bc4+3][br+16] = pf1.w;
            SP.g.Bs[bc4+0][br+32] = pf2.x; SP.g.Bs[bc4+1][br+32] = pf2.y;
            SP.g.Bs[bc4+2][br+32] = pf2.z; SP.g.Bs[bc4+3][br+32] = pf2.w;
            SP.g.Bs[bc4+0][br+48] = pf3.x; SP.g.Bs[bc4+1][br+48] = pf3.y;
            SP.g.Bs[bc4+2][br+48] = pf3.z; SP.g.Bs[bc4+3][br+48] = pf3.w;
            if (ch < 3) {
                const int kb = 64 * (ch + 1);
                pf0 = *(const float4*)&Wih[(m0 + br +  0) * HID + kb + bc4];
                pf1 = *(const float4*)&Wih[(m0 + br + 16) * HID + kb + bc4];
                pf2 = *(const float4*)&Wih[(m0 + br + 32) * HID + kb + bc4];
                pf3 = *(const float4*)&Wih[(m0 + br + 48) * HID + kb + bc4];
            }
            __syncthreads();
            const int kg = 64 * ch;
            #pragma unroll 8
            for (int kk = 0; kk < 64; kk++) {
                const float2 a = h2f(*(const __half2*)&SP.g.As[kg + kk][2 * ty]);
                const float4 bv = *(const float4*)&SP.g.Bs[kk][4 * tx];
                acc[0][0] = fmaf(a.x, bv.x, acc[0][0]); acc[0][1] = fmaf(a.x, bv.y, acc[0][1]);
                acc[0][2] = fmaf(a.x, bv.z, acc[0][2]); acc[0][3] = fmaf(a.x, bv.w, acc[0][3]);
                acc[1][0] = fmaf(a.y, bv.x, acc[1][0]); acc[1][1] = fmaf(a.y, bv.y, acc[1][1]);
                acc[1][2] = fmaf(a.y, bv.z, acc[1][2]); acc[1][3] = fmaf(a.y, bv.w, acc[1][3]);
            }
            __syncthreads();
        }
        const int mc0 = m0 + 4 * tx;
        const int gate = mc0 >> 8;
        const int kc0  = mc0 & 255;
        float bias[4];
        #pragma unroll
        for (int jj = 0; jj < 4; jj++) bias[jj] = bih[mc0 + jj] + bhh[mc0 + jj];
        #pragma unroll
        for (int i = 0; i < 2; i++) {
            const int jr = jb0 + 2 * ty + i;
            #pragma unroll
            for (int jj = 0; jj < 4; jj++)
                g_xg[jr * G4 + 4 * (kc0 + jj) + gate] = acc[i][jj] + bias[jj];
        }
    } else {
        const bool isWhh = (id < 96);
        const int tid = isWhh ? (id - 32) : (id - 96);
        const int mi  = isWhh ? (tid & 15) : (tid & 3);
        const int ki  = isWhh ? (tid >> 4) : (tid >> 2);
        const float* __restrict__ src = isWhh ? Whh : Wm;
        {
            const int c4 = (t & 15) * 4;
            const int r0 = t >> 4;
            const float4 v0 = *(const float4*)&src[(mi * 64 + r0 +  0) * HID + ki * 64 + c4];
            const float4 v1 = *(const float4*)&src[(mi * 64 + r0 + 16) * HID + ki * 64 + c4];
            const float4 v2 = *(const float4*)&src[(mi * 64 + r0 + 32) * HID + ki * 64 + c4];
            const float4 v3 = *(const float4*)&src[(mi * 64 + r0 + 48) * HID + ki * 64 + c4];
            float* T0 = SP.T + (r0 +  0) * 65; float* T1 = SP.T + (r0 + 16) * 65;
            float* T2 = SP.T + (r0 + 32) * 65; float* T3 = SP.T + (r0 + 48) * 65;
            T0[c4+0] = v0.x; T0[c4+1] = v0.y; T0[c4+2] = v0.z; T0[c4+3] = v0.w;
            T1[c4+0] = v1.x; T1[c4+1] = v1.y; T1[c4+2] = v1.z; T1[c4+3] = v1.w;
            T2[c4+0] = v2.x; T2[c4+1] = v2.y; T2[c4+2] = v2.z; T2[c4+3] = v2.w;
            T3[c4+0] = v3.x; T3[c4+1] = v3.y; T3[c4+2] = v3.z; T3[c4+3] = v3.w;
        }
        __syncthreads();
        const int m_l = t & 63, kp0 = t >> 6;
        const int rowlen = isWhh ? G4 : HID;
        __half2* __restrict__ dst = isWhh ? g_whh2 : g_wm2;
        #pragma unroll
        for (int i = 0; i < 8; i++) {
            const int kpl = kp0 + 4 * i;
            const __half2 h2 = __floats2half2_rn(SP.T[m_l * 65 + 2 * kpl], SP.T[m_l * 65 + 2 * kpl + 1]);
            dst[(ki * 32 + kpl) * rowlen + mi * 64 + m_l] = h2;
        }
    }
}

// ============================================================================
// K_h0: unchanged.
// ============================================================================
__global__ __launch_bounds__(256) void k_h0(const float* __restrict__ Wf,
                                            const float* __restrict__ bf)
{
    __shared__ float sh0[HID];
    const int j = blockIdx.x, t = threadIdx.x;
    const float4 x4 = ((const float4*)g_xg)[j * HID + t];   // (i,f,g,o)
    {
        union { __half2 h2[2]; uint2 u; } p;
        p.h2[0] = __floats2half2_rn(x4.x, x4.y);
        p.h2[1] = __floats2half2_rn(x4.z, x4.w);
        g_xgh[j * HID + t] = p.u;
    }
    const float c0 = sigm(x4.x) * tap(x4.z);
    const float h0 = sigm(x4.w) * tap(c0);
    g_c0[j * HID + t] = c0;
    g_h0[j * HID + t] = h0;
    sh0[t] = h0;
    __syncthreads();
    const int w = t >> 5, l = t & 31;
    #pragma unroll
    for (int rr = 0; rr < 2; rr++) {
        const int r = w + 8 * rr;
        float a = 0.f;
        #pragma unroll
        for (int q = 0; q < 8; q++) {
            const int k = l + 32 * q;
            a = fmaf(sh0[k], Wf[r * HID + k], a);
        }
        a += __shfl_xor_sync(0xFFFFFFFFu, a, 16);
        a += __shfl_xor_sync(0xFFFFFFFFu, a, 8);
        a += __shfl_xor_sync(0xFFFFFFFFu, a, 4);
        a += __shfl_xor_sync(0xFFFFFFFFu, a, 2);
        a += __shfl_xor_sync(0xFFFFFFFFu, a, 1);
        if (l == 0) g_sout[j * RK + r] = a + bf[r];
    }
}

// ============================================================================
// K_chain: 128 blocks x 1024 thr (round-13 change: 2x warps, phases 4-way
// split). q = t>>8 quarters the K-dim (GEMV/mid) and J-dim (cell).
// Diagnosis: issue=34% at 16 warps -> latency-bound; 32 warps/SM (8/SMSP)
// with half the per-thread serial work should roughly double issue util.
// ============================================================================
__global__ __launch_bounds__(1024) void k_chain(const int* __restrict__ xidx,
                                                const float* __restrict__ bm,
                                                const float* __restrict__ Wl,
                                                const float* __restrict__ bl,
                                                float* __restrict__ out)
{
    __shared__ __align__(16) float sh_h[2][HID];
    __shared__ __align__(16) float sh_c[2][HID];
    __shared__ __align__(16) float s_part[4][2][G4];   // 32KB phase scratch
    __shared__ __align__(16) float s_cur[2][HID];
    __shared__ float st_tot[2][RK];
    __shared__ float s_rcl[RK];

    const int t = threadIdx.x;
    const int q = t >> 8, tt = t & 255;
    const int b0 = blockIdx.x * 2;
    float* hgc = &s_part[0][0][0];   // combined hg [2][1024] (8KB)
    float* hsp = &s_part[2][0][0];   // hs partials [4q*2b][256] (8KB); combined -> [2][256]
    float* mdp = &s_part[0][0][0];   // mid partials [16][256] (16KB; hg dead)
    const __half2 h05 = __float2half2_rn(0.5f);

    // ---- Phase A: step-0 normalize + gather ----
    if (t < RK) {
        float s = 0.f;
        #pragma unroll 8
        for (int j = 0; j < NE; j++) s += g_sout[j * RK + t];
        s_rcl[t] = 1.0f / s;
    }
    if (t < 512) {
        const int b = t >> 8;
        const int sel = xidx[(b0 + b) * NSTEP + 0];
        sh_h[b][tt] = g_h0[sel * HID + tt];
        sh_c[b][tt] = g_c0[sel * HID + tt];
    }
    __syncthreads();
    if (t < 2 * RK) {
        const int b = t >> 4, r = t & 15;
        const int sel = xidx[(b0 + b) * NSTEP + 0];
        st_tot[b][r] = g_sout[sel * RK + r] * s_rcl[r];
    }

    for (int s = 1; s < NSTEP; s++) {
        __syncthreads();
        // ---- GEMV: quarter q owns kp in [q*32, q*32+32) ----
        {
            const int kpb = q * 32;
            const int mb  = tt * 4;
            float4 ac0 = {0,0,0,0}, ac1 = {0,0,0,0};
            #pragma unroll 8
            for (int kp = 0; kp < 32; kp++) {
                const uint4 w = __ldcg((const uint4*)&g_whh2[(kpb + kp) * G4 + mb]);
                const float2 hA = *(const float2*)&sh_h[0][2 * (kpb + kp)];
                const float2 hB = *(const float2*)&sh_h[1][2 * (kpb + kp)];
                const float2 p0 = h2f(*(const __half2*)&w.x);
                const float2 p1 = h2f(*(const __half2*)&w.y);
                const float2 p2 = h2f(*(const __half2*)&w.z);
                const float2 p3 = h2f(*(const __half2*)&w.w);
                ac0.x = fmaf(hA.x, p0.x, fmaf(hA.y, p0.y, ac0.x));
                ac0.y = fmaf(hA.x, p1.x, fmaf(hA.y, p1.y, ac0.y));
                ac0.z = fmaf(hA.x, p2.x, fmaf(hA.y, p2.y, ac0.z));
                ac0.w = fmaf(hA.x, p3.x, fmaf(hA.y, p3.y, ac0.w));
                ac1.x = fmaf(hB.x, p0.x, fmaf(hB.y, p0.y, ac1.x));
                ac1.y = fmaf(hB.x, p1.x, fmaf(hB.y, p1.y, ac1.y));
                ac1.z = fmaf(hB.x, p2.x, fmaf(hB.y, p2.y, ac1.z));
                ac1.w = fmaf(hB.x, p3.x, fmaf(hB.y, p3.y, ac1.w));
            }
            *(float4*)&s_part[q][0][mb] = ac0;
            *(float4*)&s_part[q][1][mb] = ac1;
        }
        __syncthreads();
        {   // combine 4 partials -> s_part[0] (2048 floats, 2 per thread)
            const int lin = t * 2;
            float2 a        = *(const float2*)(&s_part[0][0][0] + lin);
            const float2 v1 = *(const float2*)(&s_part[1][0][0] + lin);
            const float2 v2 = *(const float2*)(&s_part[2][0][0] + lin);
            const float2 v3 = *(const float2*)(&s_part[3][0][0] + lin);
            a.x += v1.x + v2.x + v3.x;
            a.y += v1.y + v2.y + v3.y;
            *(float2*)(&s_part[0][0][0] + lin) = a;
        }
        __syncthreads();
        // ---- CELL: quarter q owns j in [q*16, q*16+16), k = tt ----
        const int selb0 = xidx[b0 * NSTEP + s];
        const int selb1 = xidx[(b0 + 1) * NSTEP + s];
        const int k = tt;
        const float hgI0 = hgc[k],            hgF0 = hgc[HID + k];
        const float hgG0 = hgc[2*HID + k],    hgO0 = hgc[3*HID + k];
        const float hgI1 = hgc[G4 + k],       hgF1 = hgc[G4 + HID + k];
        const float hgG1 = hgc[G4 + 2*HID+k], hgO1 = hgc[G4 + 3*HID + k];
        const float cp0 = sh_c[0][k], cp1 = sh_c[1][k];
        __syncthreads();   // all reads done before owners overwrite sh_h/sh_c
        const __half2 HgI = __floats2half2_rn(hgI0, hgI1);
        const __half2 HgF = __floats2half2_rn(hgF0, hgF1);
        const __half2 HgG = __floats2half2_rn(hgG0, hgG1);
        const __half2 HgO = __floats2half2_rn(hgO0, hgO1);
        const __half2 cp2 = __floats2half2_rn(cp0, cp1);
        float hs0 = 0.f, hs1 = 0.f;
        const int jb = q * 16;
        #pragma unroll 4
        for (int j = jb; j < jb + 16; j++) {
            const uint2 u = g_xgh[j * HID + k];
            const __half2 xif = *(const __half2*)&u.x;   // (xi, xf)
            const __half2 xgo = *(const __half2*)&u.y;   // (xg, xo)
            const __half2 gi = __hadd2(__low2half2 (xif), HgI);
            const __half2 gf = __hadd2(__high2half2(xif), HgF);
            const __half2 gg = __hadd2(__low2half2 (xgo), HgG);
            const __half2 go = __hadd2(__high2half2(xgo), HgO);
            const __half2 iv = sigm2(gi, h05);
            const __half2 fv = sigm2(gf, h05);
            const __half2 gv = tanh2(gg);
            const __half2 ov = sigm2(go, h05);
            const __half2 cn = __hfma2(fv, cp2, __hmul2(iv, gv));
            const __half2 hn = __hmul2(ov, tanh2(cn));
            const float2 hf = h2f(hn);
            hs0 += hf.x; hs1 += hf.y;
        }
        hsp[(q * 2 + 0) * HID + k] = hs0;
        hsp[(q * 2 + 1) * HID + k] = hs1;
        // selected-j recompute in FULL f32 (recurrence-carried state)
        if ((selb0 >> 4) == q) {
            const float4 x = ((const float4*)g_xg)[selb0 * HID + k];
            const float iv = sigm(x.x + hgI0), fv = sigm(x.y + hgF0);
            const float gv = tap (x.z + hgG0), ov = sigm(x.w + hgO0);
            const float cn = fmaf(fv, cp0, iv * gv);
            sh_h[0][k] = ov * tap(cn); sh_c[0][k] = cn;
        }
        if ((selb1 >> 4) == q) {
            const float4 x = ((const float4*)g_xg)[selb1 * HID + k];
            const float iv = sigm(x.x + hgI1), fv = sigm(x.y + hgF1);
            const float gv = tap (x.z + hgG1), ov = sigm(x.w + hgO1);
            const float cn = fmaf(fv, cp1, iv * gv);
            sh_h[1][k] = ov * tap(cn); sh_c[1][k] = cn;
        }
        __syncthreads();
        if (t < 512) {   // combine hs quarters -> hsp[b*HID + k]
            const int b = t >> 8, k2 = t & 255;
            const float v = hsp[(0 + b) * HID + k2] + hsp[(2 + b) * HID + k2]
                          + hsp[(4 + b) * HID + k2] + hsp[(6 + b) * HID + k2];
            hsp[b * HID + k2] = v;
        }
        __syncthreads();

        if (s < NSTEP - 1) {
            // ---- MID: quarter q owns kp in [q*32, +32); m = tt ----
            const int kpb = q * 32;
            const int m = tt;
            float n0 = 0.f, n1 = 0.f, d0 = 0.f, d1 = 0.f;
            #pragma unroll 8
            for (int kp = 0; kp < 32; kp++) {
                const float2 w = h2f(g_wm2[(kpb + kp) * HID + m]);
                const float2 hA = *(const float2*)&sh_h[0][2 * (kpb + kp)];
                const float2 hB = *(const float2*)&sh_h[1][2 * (kpb + kp)];
                const float2 uA = *(const float2*)&hsp[0 * HID + 2 * (kpb + kp)];
                const float2 uB = *(const float2*)&hsp[1 * HID + 2 * (kpb + kp)];
                n0 = fmaf(w.x, hA.x, fmaf(w.y, hA.y, n0));
                n1 = fmaf(w.x, hB.x, fmaf(w.y, hB.y, n1));
                d0 = fmaf(w.x, uA.x, fmaf(w.y, uA.y, d0));
                d1 = fmaf(w.x, uB.x, fmaf(w.y, uB.y, d1));
            }
            mdp[(q * 4 + 0) * HID + m] = n0;
            mdp[(q * 4 + 1) * HID + m] = n1;
            mdp[(q * 4 + 2) * HID + m] = d0;
            mdp[(q * 4 + 3) * HID + m] = d1;
            __syncthreads();
            if (t < 256) {
                float n0f = 0.f, n1f = 0.f, d0f = 0.f, d1f = 0.f;
                #pragma unroll
                for (int qq = 0; qq < 4; qq++) {
                    n0f += mdp[(qq * 4 + 0) * HID + t];
                    n1f += mdp[(qq * 4 + 1) * HID + t];
                    d0f += mdp[(qq * 4 + 2) * HID + t];
                    d1f += mdp[(qq * 4 + 3) * HID + t];
                }
                const float bmv = bm[t];
                s_cur[0][t] = (n0f + bmv) * frcp(d0f + 64.0f * bmv);
                s_cur[1][t] = (n1f + bmv) * frcp(d1f + 64.0f * bmv);
            }
            __syncthreads();
            float ntot = 0.f;
            const int ub = t >> 4, ur = t & 15;
            if (t < 32) {
                #pragma unroll
                for (int r1 = 0; r1 < RK; r1++)
                    ntot = fmaf(st_tot[ub][r1], s_cur[ub][r1 * RK + ur], ntot);
            }
            __syncthreads();
            if (t < 32) st_tot[ub][ur] = ntot;
        } else {
            // ---- FINAL ----
            if (t < 64) {
                const int b = t >> 5, l = t & 31;
                const int r = l & 15, role = l >> 4;
                const float* __restrict__ src = role ? (hsp + b * HID) : &sh_h[b][0];
                float acc = 0.f;
                #pragma unroll 8
                for (int kk = 0; kk < HID; kk++)
                    acc = fmaf(Wl[r * HID + kk], src[kk], acc);
                acc += (role ? 64.0f : 1.0f) * bl[r];
                const float den = __shfl_down_sync(0xFFFFFFFFu, acc, 16);
                float v = 0.f;
                if (!role) v = st_tot[b][r] * acc * frcp(den);
                v += __shfl_xor_sync(0xFFFFFFFFu, v, 8);
                v += __shfl_xor_sync(0xFFFFFFFFu, v, 4);
                v += __shfl_xor_sync(0xFFFFFFFFu, v, 2);
                v += __shfl_xor_sync(0xFFFFFFFFu, v, 1);
                if (l == 0) out[b0 + b] = v;
            }
        }
    }
}

// ============================================================================
extern "C" void kernel_launch(void* const* d_in, const int* in_sizes, int n_in,
                              void* d_out, int out_size)
{
    (void)in_sizes; (void)n_in; (void)out_size;
    const int*   x_idx = (const int*)  d_in[0];
    const float* emb   = (const float*)d_in[1];
    const float* Wih   = (const float*)d_in[2];
    const float* Whh   = (const float*)d_in[3];
    const float* bih   = (const float*)d_in[4];
    const float* bhh   = (const float*)d_in[5];
    const float* Wf    = (const float*)d_in[6];
    const float* bf    = (const float*)d_in[7];
    const float* Wm    = (const float*)d_in[8];
    const float* bm    = (const float*)d_in[9];
    const float* Wl    = (const float*)d_in[10];
    const float* bl    = (const float*)d_in[11];
    float* out = (float*)d_out;

    k_prep <<<112, 256>>>(emb, Wih, bih, bhh, Whh, Wm);
    k_h0   <<<NE, 256>>>(Wf, bf);
    k_chain<<<BAT / 2, 1024>>>(x_idx, bm, Wl, bl, out);
}

// round 14
// speedup vs baseline: 1.2184x; 1.0787x over previous
#include <cuda_runtime.h>
#include <cuda_fp16.h>

#define HID 256
#define G4  1024
#define NE  64
#define BAT 256
#define NSTEP 6
#define RK  16

// ---------------- scratch (allocation-free: device globals) ----------------
__device__ __align__(16) float   g_xg[NE * G4];      // fp32 gate-interleaved [j][k][4]
__device__ __align__(16) uint2   g_xgh[NE * HID];    // fp16 (i,f)(g,o) packed
__device__ __align__(16) __half2 g_whh2[128 * G4];   // PW[kp][m]
__device__ __align__(16) __half2 g_wm2[128 * HID];   // PM[kp][m]
__device__ __align__(16) float   g_h0[NE * HID];
__device__ __align__(16) float   g_c0[NE * HID];
__device__ __align__(16) float   g_sout[NE * RK];

// ---------------- transcendentals ------------------------------------------
__device__ __forceinline__ float tap(float x){ float y; asm("tanh.approx.f32 %0,%1;" : "=f"(y) : "f"(x)); return y; }
__device__ __forceinline__ float frcp(float x){ float y; asm("rcp.approx.f32 %0,%1;" : "=f"(y) : "f"(x)); return y; }
__device__ __forceinline__ float sigm(float x){ return fmaf(0.5f, tap(0.5f * x), 0.5f); }
__device__ __forceinline__ float2 h2f(__half2 h){ return __half22float2(h); }
__device__ __forceinline__ __half2 tanh2(__half2 x){
    unsigned r; unsigned xi = *reinterpret_cast<unsigned*>(&x);
    asm("tanh.approx.f16x2 %0,%1;" : "=r"(r) : "r"(xi));
    return *reinterpret_cast<__half2*>(&r);
}
__device__ __forceinline__ __half2 sigm2(__half2 x, __half2 h05){
    return __hfma2(h05, tanh2(__hmul2(h05, x)), h05);
}

// ============================================================================
// K_prep: unchanged (rounds 11-13).
// ============================================================================
__global__ __launch_bounds__(256) void k_prep(const float* __restrict__ emb,
                                              const float* __restrict__ Wih,
                                              const float* __restrict__ bih,
                                              const float* __restrict__ bhh,
                                              const float* __restrict__ Whh,
                                              const float* __restrict__ Wm)
{
    __shared__ __align__(16) union {
        struct { __half As[256][34]; float Bs[64][68]; } g;
        float T[64 * 65];
    } SP;
    const int id = blockIdx.x, t = threadIdx.x;

    if (id < 32) {
        const int tx = t & 15, ty = t >> 4;
        const int jb0 = (id & 1) * 32;
        const int m0  = (id >> 1) * 64;
        {
            const int jrow = t >> 3;
            const int c0 = (t & 7) * 32;
            #pragma unroll
            for (int i = 0; i < 8; i++) {
                const float4 v = *(const float4*)&emb[(jb0 + jrow) * HID + c0 + 4 * i];
                SP.g.As[c0 + 4*i + 0][jrow] = __float2half(v.x);
                SP.g.As[c0 + 4*i + 1][jrow] = __float2half(v.y);
                SP.g.As[c0 + 4*i + 2][jrow] = __float2half(v.z);
                SP.g.As[c0 + 4*i + 3][jrow] = __float2half(v.w);
            }
        }
        const int br = t >> 4;
        const int bc4 = (t & 15) * 4;
        float4 pf0, pf1, pf2, pf3;
        {
            pf0 = *(const float4*)&Wih[(m0 + br +  0) * HID + bc4];
            pf1 = *(const float4*)&Wih[(m0 + br + 16) * HID + bc4];
            pf2 = *(const float4*)&Wih[(m0 + br + 32) * HID + bc4];
            pf3 = *(const float4*)&Wih[(m0 + br + 48) * HID + bc4];
        }
        float acc[2][4] = {};
        for (int ch = 0; ch < 4; ch++) {
            SP.g.Bs[bc4+0][br+ 0] = pf0.x; SP.g.Bs[bc4+1][br+ 0] = pf0.y;
            SP.g.Bs[bc4+2][br+ 0] = pf0.z; SP.g.Bs[bc4+3][br+ 0] = pf0.w;
            SP.g.Bs[bc4+0][br+16] = pf1.x; SP.g.Bs[bc4+1][br+16] = pf1.y;
            SP.g.Bs[bc4+2][br+16] = pf1.z; SP.g.Bs[bc4+3][br+16] = pf1.w;
            SP.g.Bs[bc4+0][br+32] = pf2.x; SP.g.Bs[bc4+1][br+32] = pf2.y;
            SP.g.Bs[bc4+2][br+32] = pf2.z; SP.g.Bs[bc4+3][br+32] = pf2.w;
            SP.g.Bs[bc4+0][br+48] = pf3.x; SP.g.Bs[bc4+1][br+48] = pf3.y;
            SP.g.Bs[bc4+2][br+48] = pf3.z; SP.g.Bs[bc4+3][br+48] = pf3.w;
            if (ch < 3) {
                const int kb = 64 * (ch + 1);
                pf0 = *(const float4*)&Wih[(m0 + br +  0) * HID + kb + bc4];
                pf1 = *(const float4*)&Wih[(m0 + br + 16) * HID + kb + bc4];
                pf2 = *(const float4*)&Wih[(m0 + br + 32) * HID + kb + bc4];
                pf3 = *(const float4*)&Wih[(m0 + br + 48) * HID + kb + bc4];
            }
            __syncthreads();
            const int kg = 64 * ch;
            #pragma unroll 8
            for (int kk = 0; kk < 64; kk++) {
                const float2 a = h2f(*(const __half2*)&SP.g.As[kg + kk][2 * ty]);
                const float4 bv = *(const float4*)&SP.g.Bs[kk][4 * tx];
                acc[0][0] = fmaf(a.x, bv.x, acc[0][0]); acc[0][1] = fmaf(a.x, bv.y, acc[0][1]);
                acc[0][2] = fmaf(a.x, bv.z, acc[0][2]); acc[0][3] = fmaf(a.x, bv.w, acc[0][3]);
                acc[1][0] = fmaf(a.y, bv.x, acc[1][0]); acc[1][1] = fmaf(a.y, bv.y, acc[1][1]);
                acc[1][2] = fmaf(a.y, bv.z, acc[1][2]); acc[1][3] = fmaf(a.y, bv.w, acc[1][3]);
            }
            __syncthreads();
        }
        const int mc0 = m0 + 4 * tx;
        const int gate = mc0 >> 8;
        const int kc0  = mc0 & 255;
        float bias[4];
        #pragma unroll
        for (int jj = 0; jj < 4; jj++) bias[jj] = bih[mc0 + jj] + bhh[mc0 + jj];
        #pragma unroll
        for (int i = 0; i < 2; i++) {
            const int jr = jb0 + 2 * ty + i;
            #pragma unroll
            for (int jj = 0; jj < 4; jj++)
                g_xg[jr * G4 + 4 * (kc0 + jj) + gate] = acc[i][jj] + bias[jj];
        }
    } else {
        const bool isWhh = (id < 96);
        const int tid = isWhh ? (id - 32) : (id - 96);
        const int mi  = isWhh ? (tid & 15) : (tid & 3);
        const int ki  = isWhh ? (tid >> 4) : (tid >> 2);
        const float* __restrict__ src = isWhh ? Whh : Wm;
        {
            const int c4 = (t & 15) * 4;
            const int r0 = t >> 4;
            const float4 v0 = *(const float4*)&src[(mi * 64 + r0 +  0) * HID + ki * 64 + c4];
            const float4 v1 = *(const float4*)&src[(mi * 64 + r0 + 16) * HID + ki * 64 + c4];
            const float4 v2 = *(const float4*)&src[(mi * 64 + r0 + 32) * HID + ki * 64 + c4];
            const float4 v3 = *(const float4*)&src[(mi * 64 + r0 + 48) * HID + ki * 64 + c4];
            float* T0 = SP.T + (r0 +  0) * 65; float* T1 = SP.T + (r0 + 16) * 65;
            float* T2 = SP.T + (r0 + 32) * 65; float* T3 = SP.T + (r0 + 48) * 65;
            T0[c4+0] = v0.x; T0[c4+1] = v0.y; T0[c4+2] = v0.z; T0[c4+3] = v0.w;
            T1[c4+0] = v1.x; T1[c4+1] = v1.y; T1[c4+2] = v1.z; T1[c4+3] = v1.w;
            T2[c4+0] = v2.x; T2[c4+1] = v2.y; T2[c4+2] = v2.z; T2[c4+3] = v2.w;
            T3[c4+0] = v3.x; T3[c4+1] = v3.y; T3[c4+2] = v3.z; T3[c4+3] = v3.w;
        }
        __syncthreads();
        const int m_l = t & 63, kp0 = t >> 6;
        const int rowlen = isWhh ? G4 : HID;
        __half2* __restrict__ dst = isWhh ? g_whh2 : g_wm2;
        #pragma unroll
        for (int i = 0; i < 8; i++) {
            const int kpl = kp0 + 4 * i;
            const __half2 h2 = __floats2half2_rn(SP.T[m_l * 65 + 2 * kpl], SP.T[m_l * 65 + 2 * kpl + 1]);
            dst[(ki * 32 + kpl) * rowlen + mi * 64 + m_l] = h2;
        }
    }
}

// ============================================================================
// K_h0: unchanged.
// ============================================================================
__global__ __launch_bounds__(256) void k_h0(const float* __restrict__ Wf,
                                            const float* __restrict__ bf)
{
    __shared__ float sh0[HID];
    const int j = blockIdx.x, t = threadIdx.x;
    const float4 x4 = ((const float4*)g_xg)[j * HID + t];   // (i,f,g,o)
    {
        union { __half2 h2[2]; uint2 u; } p;
        p.h2[0] = __floats2half2_rn(x4.x, x4.y);
        p.h2[1] = __floats2half2_rn(x4.z, x4.w);
        g_xgh[j * HID + t] = p.u;
    }
    const float c0 = sigm(x4.x) * tap(x4.z);
    const float h0 = sigm(x4.w) * tap(c0);
    g_c0[j * HID + t] = c0;
    g_h0[j * HID + t] = h0;
    sh0[t] = h0;
    __syncthreads();
    const int w = t >> 5, l = t & 31;
    #pragma unroll
    for (int rr = 0; rr < 2; rr++) {
        const int r = w + 8 * rr;
        float a = 0.f;
        #pragma unroll
        for (int q = 0; q < 8; q++) {
            const int k = l + 32 * q;
            a = fmaf(sh0[k], Wf[r * HID + k], a);
        }
        a += __shfl_xor_sync(0xFFFFFFFFu, a, 16);
        a += __shfl_xor_sync(0xFFFFFFFFu, a, 8);
        a += __shfl_xor_sync(0xFFFFFFFFu, a, 4);
        a += __shfl_xor_sync(0xFFFFFFFFu, a, 2);
        a += __shfl_xor_sync(0xFFFFFFFFu, a, 1);
        if (l == 0) g_sout[j * RK + r] = a + bf[r];
    }
}

// ============================================================================
// K_chain: 128 blocks x 1024 thr.
// Round-14 delta: GEMV inner loop rewritten with HFMA2 lane accumulation.
// sh_h2[b][kp] = (h[2kp], h[2kp+1]) fp16 shadow of sh_h, rebuilt each step by
// otherwise-idle threads inside existing barrier windows. GEMV iter: 1 LDG.128
// + 2 LDS.32 + 8 HFMA2 (no converts). half2 accumulators spilled to fp32
// every 8 kp (chunk partial ~0.02 -> fp16 rounding ~1e-5; recurrence path
// stays f32-recomputed; denominators bias-dominated).
// ============================================================================
__global__ __launch_bounds__(1024) void k_chain(const int* __restrict__ xidx,
                                                const float* __restrict__ bm,
                                                const float* __restrict__ Wl,
                                                const float* __restrict__ bl,
                                                float* __restrict__ out)
{
    __shared__ __align__(16) float sh_h[2][HID];
    __shared__ __align__(16) float sh_c[2][HID];
    __shared__ __align__(8)  __half2 sh_h2[2][HID / 2];   // fp16 k-pair shadow of sh_h
    __shared__ __align__(16) float s_part[4][2][G4];      // 32KB phase scratch
    __shared__ __align__(16) float s_cur[2][HID];
    __shared__ float st_tot[2][RK];
    __shared__ float s_rcl[RK];

    const int t = threadIdx.x;
    const int q = t >> 8, tt = t & 255;
    const int b0 = blockIdx.x * 2;
    float* hgc = &s_part[0][0][0];   // combined hg [2][1024]
    float* hsp = &s_part[2][0][0];   // hs partials; combined -> [2][256]
    float* mdp = &s_part[0][0][0];   // mid partials (hg dead)
    const __half2 h05 = __float2half2_rn(0.5f);

    // ---- Phase A: step-0 normalize + gather ----
    if (t < RK) {
        float s = 0.f;
        #pragma unroll 8
        for (int j = 0; j < NE; j++) s += g_sout[j * RK + t];
        s_rcl[t] = 1.0f / s;
    }
    if (t < 512) {
        const int b = t >> 8;
        const int sel = xidx[(b0 + b) * NSTEP + 0];
        sh_h[b][tt] = g_h0[sel * HID + tt];
        sh_c[b][tt] = g_c0[sel * HID + tt];
    }
    __syncthreads();
    if (t < 2 * RK) {
        const int b = t >> 4, r = t & 15;
        const int sel = xidx[(b0 + b) * NSTEP + 0];
        st_tot[b][r] = g_sout[sel * RK + r] * s_rcl[r];
    } else if (t >= 256 && t < 512) {
        const int e = t - 256;                       // 0..255
        const int b = e >> 7, kp = e & 127;
        sh_h2[b][kp] = __floats2half2_rn(sh_h[b][2 * kp], sh_h[b][2 * kp + 1]);
    }

    for (int s = 1; s < NSTEP; s++) {
        __syncthreads();
        // ---- GEMV (HFMA2 lanes): quarter q owns kp in [q*32, +32) ----
        {
            const int kpb = q * 32;
            const int mb  = tt * 4;
            float4 fA = {0,0,0,0}, fB = {0,0,0,0};
            #pragma unroll
            for (int c = 0; c < 4; c++) {
                __half2 aA0 = h05; aA0 = __hsub2(aA0, aA0);   // zero
                __half2 aA1 = aA0, aA2 = aA0, aA3 = aA0;
                __half2 aB0 = aA0, aB1 = aA0, aB2 = aA0, aB3 = aA0;
                #pragma unroll
                for (int i = 0; i < 8; i++) {
                    const int kp = kpb + c * 8 + i;
                    const uint4 w = __ldcg((const uint4*)&g_whh2[kp * G4 + mb]);
                    const __half2 hA2 = sh_h2[0][kp];
                    const __half2 hB2 = sh_h2[1][kp];
                    aA0 = __hfma2(*(const __half2*)&w.x, hA2, aA0);
                    aA1 = __hfma2(*(const __half2*)&w.y, hA2, aA1);
                    aA2 = __hfma2(*(const __half2*)&w.z, hA2, aA2);
                    aA3 = __hfma2(*(const __half2*)&w.w, hA2, aA3);
                    aB0 = __hfma2(*(const __half2*)&w.x, hB2, aB0);
                    aB1 = __hfma2(*(const __half2*)&w.y, hB2, aB1);
                    aB2 = __hfma2(*(const __half2*)&w.z, hB2, aB2);
                    aB3 = __hfma2(*(const __half2*)&w.w, hB2, aB3);
                }
                float2 v;
                v = h2f(aA0); fA.x += v.x + v.y;
                v = h2f(aA1); fA.y += v.x + v.y;
                v = h2f(aA2); fA.z += v.x + v.y;
                v = h2f(aA3); fA.w += v.x + v.y;
                v = h2f(aB0); fB.x += v.x + v.y;
                v = h2f(aB1); fB.y += v.x + v.y;
                v = h2f(aB2); fB.z += v.x + v.y;
                v = h2f(aB3); fB.w += v.x + v.y;
            }
            *(float4*)&s_part[q][0][mb] = fA;
            *(float4*)&s_part[q][1][mb] = fB;
        }
        __syncthreads();
        {   // combine 4 partials -> s_part[0]
            const int lin = t * 2;
            float2 a        = *(const float2*)(&s_part[0][0][0] + lin);
            const float2 v1 = *(const float2*)(&s_part[1][0][0] + lin);
            const float2 v2 = *(const float2*)(&s_part[2][0][0] + lin);
            const float2 v3 = *(const float2*)(&s_part[3][0][0] + lin);
            a.x += v1.x + v2.x + v3.x;
            a.y += v1.y + v2.y + v3.y;
            *(float2*)(&s_part[0][0][0] + lin) = a;
        }
        __syncthreads();
        // ---- CELL: quarter q owns j in [q*16, +16), k = tt ----
        const int selb0 = xidx[b0 * NSTEP + s];
        const int selb1 = xidx[(b0 + 1) * NSTEP + s];
        const int k = tt;
        const float hgI0 = hgc[k],            hgF0 = hgc[HID + k];
        const float hgG0 = hgc[2*HID + k],    hgO0 = hgc[3*HID + k];
        const float hgI1 = hgc[G4 + k],       hgF1 = hgc[G4 + HID + k];
        const float hgG1 = hgc[G4 + 2*HID+k], hgO1 = hgc[G4 + 3*HID + k];
        const float cp0 = sh_c[0][k], cp1 = sh_c[1][k];
        __syncthreads();   // reads done before owners overwrite sh_h/sh_c
        const __half2 HgI = __floats2half2_rn(hgI0, hgI1);
        const __half2 HgF = __floats2half2_rn(hgF0, hgF1);
        const __half2 HgG = __floats2half2_rn(hgG0, hgG1);
        const __half2 HgO = __floats2half2_rn(hgO0, hgO1);
        const __half2 cp2 = __floats2half2_rn(cp0, cp1);
        float hs0 = 0.f, hs1 = 0.f;
        const int jb = q * 16;
        #pragma unroll 4
        for (int j = jb; j < jb + 16; j++) {
            const uint2 u = g_xgh[j * HID + k];
            const __half2 xif = *(const __half2*)&u.x;
            const __half2 xgo = *(const __half2*)&u.y;
            const __half2 gi = __hadd2(__low2half2 (xif), HgI);
            const __half2 gf = __hadd2(__high2half2(xif), HgF);
            const __half2 gg = __hadd2(__low2half2 (xgo), HgG);
            const __half2 go = __hadd2(__high2half2(xgo), HgO);
            const __half2 iv = sigm2(gi, h05);
            const __half2 fv = sigm2(gf, h05);
            const __half2 gv = tanh2(gg);
            const __half2 ov = sigm2(go, h05);
            const __half2 cn = __hfma2(fv, cp2, __hmul2(iv, gv));
            const __half2 hn = __hmul2(ov, tanh2(cn));
            const float2 hf = h2f(hn);
            hs0 += hf.x; hs1 += hf.y;
        }
        hsp[(q * 2 + 0) * HID + k] = hs0;
        hsp[(q * 2 + 1) * HID + k] = hs1;
        // selected-j recompute in FULL f32
        if ((selb0 >> 4) == q) {
            const float4 x = ((const float4*)g_xg)[selb0 * HID + k];
            const float iv = sigm(x.x + hgI0), fv = sigm(x.y + hgF0);
            const float gv = tap (x.z + hgG0), ov = sigm(x.w + hgO0);
            const float cn = fmaf(fv, cp0, iv * gv);
            sh_h[0][k] = ov * tap(cn); sh_c[0][k] = cn;
        }
        if ((selb1 >> 4) == q) {
            const float4 x = ((const float4*)g_xg)[selb1 * HID + k];
            const float iv = sigm(x.x + hgI1), fv = sigm(x.y + hgF1);
            const float gv = tap (x.z + hgG1), ov = sigm(x.w + hgO1);
            const float cn = fmaf(fv, cp1, iv * gv);
            sh_h[1][k] = ov * tap(cn); sh_c[1][k] = cn;
        }
        __syncthreads();
        if (t < 512) {   // combine hs quarters
            const int b = t >> 8, k2 = t & 255;
            const float v = hsp[(0 + b) * HID + k2] + hsp[(2 + b) * HID + k2]
                          + hsp[(4 + b) * HID + k2] + hsp[(6 + b) * HID + k2];
            hsp[b * HID + k2] = v;
        } else if (t < 768) {   // rebuild fp16 h shadow for next GEMV
            const int e = t - 512;
            const int b = e >> 7, kp = e & 127;
            sh_h2[b][kp] = __floats2half2_rn(sh_h[b][2 * kp], sh_h[b][2 * kp + 1]);
        }
        __syncthreads();

        if (s < NSTEP - 1) {
            // ---- MID: quarter q owns kp in [q*32, +32); m = tt ----
            const int kpb = q * 32;
            const int m = tt;
            float n0 = 0.f, n1 = 0.f, d0 = 0.f, d1 = 0.f;
            #pragma unroll 8
            for (int kp = 0; kp < 32; kp++) {
                const float2 w = h2f(g_wm2[(kpb + kp) * HID + m]);
                const float2 hA = *(const float2*)&sh_h[0][2 * (kpb + kp)];
                const float2 hB = *(const float2*)&sh_h[1][2 * (kpb + kp)];
                const float2 uA = *(const float2*)&hsp[0 * HID + 2 * (kpb + kp)];
                const float2 uB = *(const float2*)&hsp[1 * HID + 2 * (kpb + kp)];
                n0 = fmaf(w.x, hA.x, fmaf(w.y, hA.y, n0));
                n1 = fmaf(w.x, hB.x, fmaf(w.y, hB.y, n1));
                d0 = fmaf(w.x, uA.x, fmaf(w.y, uA.y, d0));
                d1 = fmaf(w.x, uB.x, fmaf(w.y, uB.y, d1));
            }
            mdp[(q * 4 + 0) * HID + m] = n0;
            mdp[(q * 4 + 1) * HID + m] = n1;
            mdp[(q * 4 + 2) * HID + m] = d0;
            mdp[(q * 4 + 3) * HID + m] = d1;
            __syncthreads();
            if (t < 256) {
                float n0f = 0.f, n1f = 0.f, d0f = 0.f, d1f = 0.f;
                #pragma unroll
                for (int qq = 0; qq < 4; qq++) {
                    n0f += mdp[(qq * 4 + 0) * HID + t];
                    n1f += mdp[(qq * 4 + 1) * HID + t];
                    d0f += mdp[(qq * 4 + 2) * HID + t];
                    d1f += mdp[(qq * 4 + 3) * HID + t];
                }
                const float bmv = bm[t];
                s_cur[0][t] = (n0f + bmv) * frcp(d0f + 64.0f * bmv);
                s_cur[1][t] = (n1f + bmv) * frcp(d1f + 64.0f * bmv);
            }
            __syncthreads();
            float ntot = 0.f;
            const int ub = t >> 4, ur = t & 15;
            if (t < 32) {
                #pragma unroll
                for (int r1 = 0; r1 < RK; r1++)
                    ntot = fmaf(st_tot[ub][r1], s_cur[ub][r1 * RK + ur], ntot);
            }
            __syncthreads();
            if (t < 32) st_tot[ub][ur] = ntot;
        } else {
            // ---- FINAL ----
            if (t < 64) {
                const int b = t >> 5, l = t & 31;
                const int r = l & 15, role = l >> 4;
                const float* __restrict__ src = role ? (hsp + b * HID) : &sh_h[b][0];
                float acc = 0.f;
                #pragma unroll 8
                for (int kk = 0; kk < HID; kk++)
                    acc = fmaf(Wl[r * HID + kk], src[kk], acc);
                acc += (role ? 64.0f : 1.0f) * bl[r];
                const float den = __shfl_down_sync(0xFFFFFFFFu, acc, 16);
                float v = 0.f;
                if (!role) v = st_tot[b][r] * acc * frcp(den);
                v += __shfl_xor_sync(0xFFFFFFFFu, v, 8);
                v += __shfl_xor_sync(0xFFFFFFFFu, v, 4);
                v += __shfl_xor_sync(0xFFFFFFFFu, v, 2);
                v += __shfl_xor_sync(0xFFFFFFFFu, v, 1);
                if (l == 0) out[b0 + b] = v;
            }
        }
    }
}

// ============================================================================
extern "C" void kernel_launch(void* const* d_in, const int* in_sizes, int n_in,
                              void* d_out, int out_size)
{
    (void)in_sizes; (void)n_in; (void)out_size;
    const int*   x_idx = (const int*)  d_in[0];
    const float* emb   = (const float*)d_in[1];
    const float* Wih   = (const float*)d_in[2];
    const float* Whh   = (const float*)d_in[3];
    const float* bih   = (const float*)d_in[4];
    const float* bhh   = (const float*)d_in[5];
    const float* Wf    = (const float*)d_in[6];
    const float* bf    = (const float*)d_in[7];
    const float* Wm    = (const float*)d_in[8];
    const float* bm    = (const float*)d_in[9];
    const float* Wl    = (const float*)d_in[10];
    const float* bl    = (const float*)d_in[11];
    float* out = (float*)d_out;

    k_prep <<<112, 256>>>(emb, Wih, bih, bhh, Whh, Wm);
    k_h0   <<<NE, 256>>>(Wf, bf);
    k_chain<<<BAT / 2, 1024>>>(x_idx, bm, Wl, bl, out);
}